// round 10
// baseline (speedup 1.0000x reference)
#include <cuda_runtime.h>
#include <cuda_bf16.h>

// ---------------------------------------------------------------------------
// Compile-time D4 codebook (values stored as integers = 2*g, in {±1,±3,±5}),
// replicated exactly from the reference _code8_to_d4 builder.
// ---------------------------------------------------------------------------
__host__ __device__ constexpr int cw2(int i8, int j) {
    int v[4] = {0, 0, 0, 0};
    int b = i8 & 31;
    if (b < 16) {
        if (b < 8) {
            if (b < 2) {
                if (b < 1) { v[0] = 1; v[1] = 1; v[2] = 1; v[3] = 1; }
                else       { v[0] = 3; v[1] = 3; v[2] = 3; v[3] = 3; }
            } else {
                int ibx = b >> 1;
                if (b & 1) { v[0] = 1; v[1] = 1; v[2] = 1; v[3] = 1; v[0] = 3; v[ibx] = 3; }
                else       { v[0] = 3; v[1] = 3; v[2] = 3; v[3] = 3; v[0] = 1; v[ibx] = 1; }
            }
        } else {
            int ibx = b & 3;
            if (b < 12) { v[0] = 1; v[1] = 1; v[2] = 1; v[3] = 1; v[ibx] = 3; }
            else        { v[0] = 3; v[1] = 3; v[2] = 3; v[3] = 3; v[ibx] = 1; }
        }
    } else if (b < 20) {
        int ibx = b & 3;
        v[0] = 1; v[1] = 1; v[2] = 1; v[3] = 1; v[ibx] = 5;
    } else {
        int ibx = b - 20;
        int ib4 = ibx & 3;
        int ib3 = ibx >> 2;
        v[0] = 1; v[1] = 1; v[2] = 1; v[3] = 1;
        v[ib4] = 3;
        if (ib3 >= ib4) ib3 += 1;
        v[ib3] = 5;
    }
    if (i8 & 32) v[2] = -v[2];
    if (i8 & 64) v[1] = -v[1];
    int s = v[0] + v[1] + v[2] + v[3];   // 2 * sum(x), always even
    int sumx = s / 2;
    if (sumx & 1) v[3] = -v[3];
    if (i8 & 128) { v[0] = -v[0]; v[1] = -v[1]; v[2] = -v[2]; v[3] = -v[3]; }
    return v[j];
}

__host__ __device__ constexpr int cnorm(int i8) {
    int s = 0;
    for (int j = 0; j < 4; j++) { int v = cw2(i8, j); s += v * v; }
    return s / 4;   // |g|^2 in {1,3,5,7,9}, exact
}

// magnitude index (0=0.5, 1=1.5, 2=2.5) of pattern P, coord j
__host__ __device__ constexpr int mag(int P, int j) {
    int c = cw2(P, j);
    int a = c < 0 ? -c : c;
    return (a - 1) / 2;
}
// per-coordinate squared magnitude (exact in fp32)
__host__ __device__ constexpr float gsq(int m) {
    return m == 0 ? 0.25f : (m == 1 ? 2.25f : 6.25f);
}
// parity-class bit of pattern: parity of count of 1.5-magnitude coordinates.
// A sign assignment s is representable iff (#neg(s) mod 2) == bsel(P).
__host__ __device__ constexpr int bsel(int P) {
    int s = 0;
    for (int j = 0; j < 4; j++) s += 2 * mag(P, j) + 1;
    return (s % 4) / 2;
}

// ---- codeword float table for exact recovery / slow path -------------------
struct F4 { float x, y, z, w; };
struct G4 { F4 v[128]; };
__host__ __device__ constexpr G4 mkf4() {
    G4 t{};
    for (int k = 0; k < 128; k++) {
        t.v[k].x = (float)cw2(k, 0) * 0.5f;
        t.v[k].y = (float)cw2(k, 1) * 0.5f;
        t.v[k].z = (float)cw2(k, 2) * 0.5f;
        t.v[k].w = (float)cw2(k, 3) * 0.5f;
    }
    return t;
}
__device__ __align__(16) const G4 g_f4 = mkf4();

struct NN { float v[32]; };
__host__ __device__ constexpr NN mknn() {
    NN t{};
    for (int P = 0; P < 32; P++) t.v[P] = -(float)cnorm(P);
    return t;
}
__device__ const NN g_nn = mknn();

// ---------------------------------------------------------------------------
// Phase 1: per magnitude pattern (8 even-parity sign candidates each),
//   halfscore sh = (s01 + c01) + (s23 + c23) - wrong*2*min4
//     where c01 = 16 - 0.5*(g0^2+g1^2), c23 = -0.5*(g2^2+g3^2)
//     (8 distinct (s01+c01) / (s23+c23) terms CSE across the 32 patterns)
//   packed u = (bits(sh) & ~31) | P  -> argmax via unsigned max (sh > 0 always)
// best/second tracked in 4 independent lanes (P mod 4) to break the
// sequential dependence chain; merged after the sweep.
// ---------------------------------------------------------------------------
template <int P>
struct Pat1 {
    static __device__ __forceinline__ void run(const float (&A)[3][4],
                                               float npm0, float npm1,
                                               unsigned (&B)[4], unsigned (&S)[4]) {
        constexpr int i0 = mag(P, 0), i1 = mag(P, 1), i2 = mag(P, 2), i3 = mag(P, 3);
        constexpr float c01 = 16.0f - 0.5f * (gsq(i0) + gsq(i1));
        constexpr float c23 = -0.5f * (gsq(i2) + gsq(i3));
        constexpr int L = P & 3;
        float t01 = (A[i0][0] + A[i1][1]) + c01;
        float t23 = (A[i2][2] + A[i3][3]) + c23;
        float mn  = fminf(fminf(A[i0][0], A[i1][1]), fminf(A[i2][2], A[i3][3]));
        float sh  = fmaf(bsel(P) ? npm1 : npm0, mn, t01 + t23);
        unsigned u = (__float_as_uint(sh) & 0xFFFFFFE0u) | (unsigned)P;
        unsigned t = min(u, B[L]);
        S[L] = max(S[L], t);
        B[L] = max(B[L], u);
        Pat1<P + 1>::run(A, npm0, npm1, B, S);
    }
};
template <>
struct Pat1<32> {
    static __device__ __forceinline__ void run(const float (&)[3][4], float, float,
                                               unsigned (&)[4], unsigned (&)[4]) {}
};

template <bool IDX_FLOAT>
__global__ __launch_bounds__(256, 5) void d4_kernel(const float4* __restrict__ X,
                                                    const float4* __restrict__ grid,
                                                    float* __restrict__ out,
                                                    int n) {
    int i = blockIdx.x * blockDim.x + threadIdx.x;
    if (i >= n) return;

    float4 x = X[i];

    // 12 shared magnitude products m*|x_j| (abs folds into FMUL modifier)
    float A[3][4];
    A[0][0] = 0.5f * fabsf(x.x); A[1][0] = 1.5f * fabsf(x.x); A[2][0] = 2.5f * fabsf(x.x);
    A[0][1] = 0.5f * fabsf(x.y); A[1][1] = 1.5f * fabsf(x.y); A[2][1] = 2.5f * fabsf(x.y);
    A[0][2] = 0.5f * fabsf(x.z); A[1][2] = 1.5f * fabsf(x.z); A[2][2] = 2.5f * fabsf(x.z);
    A[0][3] = 0.5f * fabsf(x.w); A[1][3] = 1.5f * fabsf(x.w); A[2][3] = 2.5f * fabsf(x.w);

    // parity of negative-coordinate count
    unsigned sb = (__float_as_uint(x.x) ^ __float_as_uint(x.y)) ^
                  (__float_as_uint(x.z) ^ __float_as_uint(x.w));
    int parbit = (int)(sb >> 31);
    // flip penalty is 2 * min product: npm in {0, -2}
    // B=0 patterns wrong iff parbit=1; B=1 patterns wrong iff parbit=0
    float npm0 = parbit ? -2.0f : 0.0f;
    float npm1 = parbit ? 0.0f : -2.0f;

    unsigned B[4] = {0u, 0u, 0u, 0u};
    unsigned S[4] = {0u, 0u, 0u, 0u};
    Pat1<0>::run(A, npm0, npm1, B, S);

    // merge the 4 (best, second) lanes: 2 levels
    unsigned b01 = max(B[0], B[1]);
    unsigned s01 = max(min(B[0], B[1]), max(S[0], S[1]));
    unsigned b23 = max(B[2], B[3]);
    unsigned s23m = max(min(B[2], B[3]), max(S[2], S[3]));
    unsigned best   = max(b01, b23);
    unsigned second = max(min(b01, b23), max(s01, s23m));

    int bp = (int)(best & 31u);

    // ---- δ-guard: if runner-up within 128 ULP-ints, resolve exactly --------
    if (best - second < 128u) {
        const float4* gt = reinterpret_cast<const float4*>(g_f4.v);
        float bs = -3.0e38f;
        int bpp = 0;
#pragma unroll 1
        for (int P = 0; P < 32; P++) {
            float gm = 0.0f;
#pragma unroll
            for (int v = 0; v < 4; v++) {
                float4 g = gt[P + (v << 5)];
                float d = x.x * g.x;
                d = fmaf(x.y, g.y, d);
                d = fmaf(x.z, g.z, d);
                d = fmaf(x.w, g.w, d);
                gm = fmaxf(gm, fabsf(d));
            }
            float s = fmaf(gm, 2.0f, g_nn.v[P]);
            if (s > bs) { bs = s; bpp = P; }   // strict >: lowest pattern wins ties
        }
        bp = bpp;
    }

    // ---- recovery: exact reference-chain dots for the 4 variants of bp -----
    const float4* gt = reinterpret_cast<const float4*>(g_f4.v);
    float dv[4];
#pragma unroll
    for (int v = 0; v < 4; v++) {
        float4 g = gt[bp + (v << 5)];
        float d = x.x * g.x;
        d = fmaf(x.y, g.y, d);
        d = fmaf(x.z, g.z, d);
        d = fmaf(x.w, g.w, d);
        dv[v] = d;
    }
    float gmr = fmaxf(fmaxf(fabsf(dv[0]), fabsf(dv[1])),
                      fmaxf(fabsf(dv[2]), fabsf(dv[3])));
    int kk = bp;
    bool found = false;
#pragma unroll
    for (int v = 0; v < 4; v++) {
        bool hit = (!found) && (fabsf(dv[v]) == gmr);
        if (hit) kk = (bp + (v << 5)) | ((dv[v] < 0.0f) ? 128 : 0);
        found = found || hit;
    }

    // winner codeword values read from harness grid -> bit-exact
    reinterpret_cast<float4*>(out)[i] = grid[kk];

    if (IDX_FLOAT) {
        out[(long long)4 * n + i] = (float)kk;
    } else {
        reinterpret_cast<unsigned char*>(out)[(long long)16 * n + i] = (unsigned char)kk;
    }
}

extern "C" void kernel_launch(void* const* d_in, const int* in_sizes, int n_in,
                              void* d_out, int out_size) {
    const float4* X    = (const float4*)d_in[0];
    const float4* grid = (const float4*)d_in[1];
    // d_in[2] = grid_norm, unneeded: norms are the exact constants {1,3,5,7,9}

    int n = in_sizes[0] / 4;
    int blocks = (n + 255) / 256;

    long long out5 = 5LL * n;
    if ((long long)out_size >= out5) {
        d4_kernel<true><<<blocks, 256>>>(X, grid, (float*)d_out, n);
    } else {
        d4_kernel<false><<<blocks, 256>>>(X, grid, (float*)d_out, n);
    }
}

// round 12
// speedup vs baseline: 1.5028x; 1.5028x over previous
#include <cuda_runtime.h>
#include <cuda_bf16.h>

// ---------------------------------------------------------------------------
// Compile-time D4 codebook (values stored as integers = 2*g, in {±1,±3,±5}),
// replicated exactly from the reference _code8_to_d4 builder.
// ---------------------------------------------------------------------------
__host__ __device__ constexpr int cw2(int i8, int j) {
    int v[4] = {0, 0, 0, 0};
    int b = i8 & 31;
    if (b < 16) {
        if (b < 8) {
            if (b < 2) {
                if (b < 1) { v[0] = 1; v[1] = 1; v[2] = 1; v[3] = 1; }
                else       { v[0] = 3; v[1] = 3; v[2] = 3; v[3] = 3; }
            } else {
                int ibx = b >> 1;
                if (b & 1) { v[0] = 1; v[1] = 1; v[2] = 1; v[3] = 1; v[0] = 3; v[ibx] = 3; }
                else       { v[0] = 3; v[1] = 3; v[2] = 3; v[3] = 3; v[0] = 1; v[ibx] = 1; }
            }
        } else {
            int ibx = b & 3;
            if (b < 12) { v[0] = 1; v[1] = 1; v[2] = 1; v[3] = 1; v[ibx] = 3; }
            else        { v[0] = 3; v[1] = 3; v[2] = 3; v[3] = 3; v[ibx] = 1; }
        }
    } else if (b < 20) {
        int ibx = b & 3;
        v[0] = 1; v[1] = 1; v[2] = 1; v[3] = 1; v[ibx] = 5;
    } else {
        int ibx = b - 20;
        int ib4 = ibx & 3;
        int ib3 = ibx >> 2;
        v[0] = 1; v[1] = 1; v[2] = 1; v[3] = 1;
        v[ib4] = 3;
        if (ib3 >= ib4) ib3 += 1;
        v[ib3] = 5;
    }
    if (i8 & 32) v[2] = -v[2];
    if (i8 & 64) v[1] = -v[1];
    int s = v[0] + v[1] + v[2] + v[3];   // 2 * sum(x), always even
    int sumx = s / 2;
    if (sumx & 1) v[3] = -v[3];
    if (i8 & 128) { v[0] = -v[0]; v[1] = -v[1]; v[2] = -v[2]; v[3] = -v[3]; }
    return v[j];
}

__host__ __device__ constexpr int cnorm(int i8) {
    int s = 0;
    for (int j = 0; j < 4; j++) { int v = cw2(i8, j); s += v * v; }
    return s / 4;   // |g|^2 in {1,3,5,7,9}, exact
}

// ---- codeword float table for the exact slow path --------------------------
struct F4 { float x, y, z, w; };
struct G4 { F4 v[128]; };
__host__ __device__ constexpr G4 mkf4() {
    G4 t{};
    for (int k = 0; k < 128; k++) {
        t.v[k].x = (float)cw2(k, 0) * 0.5f;
        t.v[k].y = (float)cw2(k, 1) * 0.5f;
        t.v[k].z = (float)cw2(k, 2) * 0.5f;
        t.v[k].w = (float)cw2(k, 3) * 0.5f;
    }
    return t;
}
__device__ __align__(16) const G4 g_f4 = mkf4();

struct NN { float v[32]; };
__host__ __device__ constexpr NN mknn() {
    NN t{};
    for (int P = 0; P < 32; P++) t.v[P] = -(float)cnorm(P);
    return t;
}
__device__ const NN g_nn = mknn();

// ---- inverse table: (mag-codes, sign bits) -> codebook index ---------------
// per coord: m in {0,1,2} for |g| in {0.5,1.5,2.5}; cm = sum m_j << 2j (8 bits)
// sb = sum sign_j << j (4 bits). inv[cm | sb<<8] = k. Bijective on the 256
// valid codes; unused slots stay 0 and are never queried.
struct IT { unsigned char v[4096]; };
__host__ __device__ constexpr IT mkinv() {
    IT t{};
    for (int k = 0; k < 256; k++) {
        unsigned cm = 0, sb = 0;
        for (int j = 0; j < 4; j++) {
            int c2 = cw2(k, j);
            int a = c2 < 0 ? -c2 : c2;
            cm |= (unsigned)((a - 1) / 2) << (2 * j);
            sb |= (unsigned)(c2 < 0 ? 1 : 0) << j;
        }
        t.v[cm | (sb << 8)] = (unsigned char)k;
    }
    return t;
}
__device__ const IT g_inv = mkinv();

// ---------------------------------------------------------------------------
// Exact slow path (rare): reference-chain scan over all 32 patterns x 4
// variants, then exact recovery with ascending-index tie order. This is the
// R9 code path that measured rel_err = 0.0.
// ---------------------------------------------------------------------------
__device__ __noinline__ int slow_exact(float4 x) {
    const float4* gt = reinterpret_cast<const float4*>(g_f4.v);
    float bs = -3.0e38f;
    int bp = 0;
#pragma unroll 1
    for (int P = 0; P < 32; P++) {
        float gm = 0.0f;
#pragma unroll
        for (int v = 0; v < 4; v++) {
            float4 g = gt[P + (v << 5)];
            float d = x.x * g.x;
            d = fmaf(x.y, g.y, d);
            d = fmaf(x.z, g.z, d);
            d = fmaf(x.w, g.w, d);
            gm = fmaxf(gm, fabsf(d));
        }
        float s = fmaf(gm, 2.0f, g_nn.v[P]);
        if (s > bs) { bs = s; bp = P; }   // strict >: lowest pattern wins ties
    }
    float dv[4];
#pragma unroll
    for (int v = 0; v < 4; v++) {
        float4 g = gt[bp + (v << 5)];
        float d = x.x * g.x;
        d = fmaf(x.y, g.y, d);
        d = fmaf(x.z, g.z, d);
        d = fmaf(x.w, g.w, d);
        dv[v] = d;
    }
    float gmr = fmaxf(fmaxf(fabsf(dv[0]), fabsf(dv[1])),
                      fmaxf(fabsf(dv[2]), fabsf(dv[3])));
    int kk = bp;
    bool found = false;
#pragma unroll
    for (int v = 0; v < 4; v++) {
        bool hit = (!found) && (fabsf(dv[v]) == gmr);
        if (hit) kk = (bp + (v << 5)) | ((dv[v] < 0.0f) ? 128 : 0);
        found = found || hit;
    }
    return kk;
}

// compare-exchange (descending) on index-tagged magnitude uints
#define CE_DESC(p, q) { unsigned _hi = max(p, q), _lo = min(p, q); p = _hi; q = _lo; }

template <bool IDX_FLOAT>
__global__ __launch_bounds__(256) void d4_kernel(const float4* __restrict__ X,
                                                 const float4* __restrict__ grid,
                                                 float* __restrict__ out,
                                                 int n) {
    int i = blockIdx.x * blockDim.x + threadIdx.x;
    if (i >= n) return;

    float4 x = X[i];
    unsigned ux0 = __float_as_uint(x.x);
    unsigned ux1 = __float_as_uint(x.y);
    unsigned ux2 = __float_as_uint(x.z);
    unsigned ux3 = __float_as_uint(x.w);

    // |x| with low 2 mantissa bits replaced by the coordinate index
    unsigned t0 = (ux0 & 0x7FFFFFFCu) | 0u;
    unsigned t1 = (ux1 & 0x7FFFFFFCu) | 1u;
    unsigned t2 = (ux2 & 0x7FFFFFFCu) | 2u;
    unsigned t3 = (ux3 & 0x7FFFFFFCu) | 3u;

    // sort descending: t0 >= t1 >= t2 >= t3 (positive floats == uint order)
    CE_DESC(t0, t1); CE_DESC(t2, t3); CE_DESC(t0, t2); CE_DESC(t1, t3); CE_DESC(t1, t2);

    float y1 = __uint_as_float(t0 & ~3u);
    float y2 = __uint_as_float(t1 & ~3u);
    float y3 = __uint_as_float(t2 & ~3u);
    float y4 = __uint_as_float(t3 & ~3u);

    // parity of negative-coordinate count
    unsigned parbit = ((ux0 ^ ux1) ^ (ux2 ^ ux3)) >> 31;

    // shared partial sums
    float q34  = y3 + y4;
    float q12  = y1 + y2;
    float q234 = y2 + q34;
    float T    = y1 + q234;
    float y123 = q12 + y3;

    // parity penalty activations (u = y4 when this parity class is "wrong")
    float u0 = parbit ? y4 : 0.0f;   // multisets with even #1.5 (bsel=0)
    float u1 = parbit ? 0.0f : y4;   // multisets with odd  #1.5 (bsel=1)

    // 7 multiset halfscores, offset +32 so all are positive:
    //   sh = sum(m_r * y_r) - penalty + (32 - n/2)
    float sh0 = fmaf(0.5f, T, 31.5f - u0);                               // {.5^4}      n=1
    float sh1 = fmaf(1.5f, T, fmaf(-3.0f, u0, 27.5f));                   // {1.5^4}     n=9 pen=3y4
    float sh2 = fmaf(1.5f, q12, fmaf(0.5f, q34, 29.5f - u0));            // {1.5^2,.5^2} n=5
    float sh3 = fmaf(1.5f, y1, fmaf(0.5f, q234, 30.5f - u1));            // {1.5,.5^3}  n=3
    float sh4 = fmaf(1.5f, y123, fmaf(0.5f, y4, 28.5f - u1));            // {1.5^3,.5}  n=7
    float sh5 = fmaf(2.5f, y1, fmaf(0.5f, q234, 28.5f - u0));            // {2.5,.5^3}  n=7
    float sh6 = fmaf(2.5f, y1, fmaf(1.5f, y2, fmaf(0.5f, q34, 27.5f - u1))); // {2.5,1.5,.5^2} n=9

    // argmax with 3-bit id packed into the mantissa; track best + second
    unsigned best = 0u, second = 0u;
    {
        float sh[7] = {sh0, sh1, sh2, sh3, sh4, sh5, sh6};
#pragma unroll
        for (int m = 0; m < 7; m++) {
            unsigned u = (__float_as_uint(sh[m]) & 0xFFFFFFF8u) | (unsigned)m;
            unsigned t = min(u, best);
            second = max(second, t);
            best   = max(best, u);
        }
    }

    // guard: near-tie between multisets, or tied/zero magnitudes -> exact path
    bool near = (best - second) < 128u;
    bool tie  = (((t0 ^ t1) & 0xFFFFFFFCu) == 0u) |
                (((t1 ^ t2) & 0xFFFFFFFCu) == 0u) |
                (((t2 ^ t3) & 0xFFFFFFFCu) == 0u) |
                ((t3 & 0xFFFFFFFCu) == 0u);

    int kk;
    if (near | tie) {
        kk = slow_exact(x);
    } else {
        unsigned Mid = best & 7u;
        // bsel bits for multiset ids {3,4,6} -> 0x58; wrong parity flips sign at i_min
        unsigned w = ((0x58u >> Mid) & 1u) ^ parbit;
        // mags-by-rank byte for each multiset id (rank0 in low 2 bits)
        unsigned mcb = __byte_perm(0x01055500u, 0x00060215u, Mid);
        // scatter rank-mags to coordinates via the sort permutation
        unsigned cm = ((mcb)&3u) << (2u * (t0 & 3u));
        cm |= ((mcb >> 2) & 3u) << (2u * (t1 & 3u));
        cm |= ((mcb >> 4) & 3u) << (2u * (t2 & 3u));
        cm |= ((mcb >> 6) & 3u) << (2u * (t3 & 3u));
        // natural signs, with the min coordinate flipped when parity is wrong
        unsigned sbits = (ux0 >> 31) | ((ux1 >> 31) << 1) |
                         ((ux2 >> 31) << 2) | ((ux3 >> 31) << 3);
        sbits ^= w << (t3 & 3u);
        kk = (int)g_inv.v[cm | (sbits << 8)];
    }

    // winner codeword values read from harness grid -> bit-exact
    reinterpret_cast<float4*>(out)[i] = grid[kk];

    if (IDX_FLOAT) {
        out[(long long)4 * n + i] = (float)kk;
    } else {
        reinterpret_cast<unsigned char*>(out)[(long long)16 * n + i] = (unsigned char)kk;
    }
}

extern "C" void kernel_launch(void* const* d_in, const int* in_sizes, int n_in,
                              void* d_out, int out_size) {
    const float4* X    = (const float4*)d_in[0];
    const float4* grid = (const float4*)d_in[1];
    // d_in[2] = grid_norm, unneeded: norms are the exact constants {1,3,5,7,9}

    int n = in_sizes[0] / 4;
    int blocks = (n + 255) / 256;

    long long out5 = 5LL * n;
    if ((long long)out_size >= out5) {
        d4_kernel<true><<<blocks, 256>>>(X, grid, (float*)d_out, n);
    } else {
        d4_kernel<false><<<blocks, 256>>>(X, grid, (float*)d_out, n);
    }
}